// round 5
// baseline (speedup 1.0000x reference)
#include <cuda_runtime.h>

#define M_MOL 64
#define NA    24
#define P     276
#define T_ROWS 6000
#define TT    48
#define NBLK  125
#define NTHR  768
#define QC    0.22360679774997896f   // sqrt(5)/sig, sig=10
#define C0    0.0166666666666667f    // 5/(3*sig^2)
#define PPAD  288
#define PHALF 138

// ---------------- global scratch ----------------
__device__ float g_Apart [NBLK * M_MOL * P];
__device__ float g_S1part[NBLK * M_MOL];
__device__ float g_Espart[NBLK * M_MOL];
__device__ unsigned g_phase;   // zero-init, monotonic across replays
__device__ int      g_cnt;     // returns to 0 each call

// ---------------- f32x2 helpers ----------------
typedef unsigned long long u64;
__device__ __forceinline__ u64 pk2(float lo, float hi) {
    u64 r; asm("mov.b64 %0, {%1,%2};" : "=l"(r) : "f"(lo), "f"(hi)); return r;
}
__device__ __forceinline__ u64 fma2(u64 a, u64 b, u64 c) {
    u64 d; asm("fma.rn.f32x2 %0, %1, %2, %3;" : "=l"(d) : "l"(a), "l"(b), "l"(c)); return d;
}
__device__ __forceinline__ void upk2(u64 v, float& lo, float& hi) {
    asm("mov.b64 {%0,%1}, %2;" : "=f"(lo), "=f"(hi) : "l"(v));
}

// smem layout (floats):
//  sX   @0      [48][288]  13824
//  sJ   @13824  [48][288]  13824
//  sQx  @27648  [276][64]  17664   (sG1 @27648 [48][64], sG2 @30720 [48][64] alias after phase A)
//  sW1d @45312  [48][128]   6144   (sRs aliases here before phase A)
//  sW2  @51456  [48][64]    3072
//  sDot @54528  [48][64]    3072
//  sTn  @57600  [48]
//  sTc  @57648  [48]
//  sNrm @57696  [64]        -> 57760 floats = 231040 B
#define SMEM_FLOATS 57760
#define SMEM_BYTES  (SMEM_FLOATS * 4)

__global__ __launch_bounds__(NTHR, 1)
void k_all(const float* __restrict__ Rs, const float* __restrict__ xst,
           const float* __restrict__ Jx, float* __restrict__ out) {
    extern __shared__ float sm[];
    float* sX   = sm;
    float* sJ   = sm + 13824;
    float* sQx  = sm + 27648;
    float* sG1  = sm + 27648;    // alias (valid after phase-A sync)
    float* sG2  = sm + 30720;
    float* sW1d = sm + 45312;
    float* sW2  = sm + 51456;
    float* sDot = sm + 54528;
    float* sTn  = sm + 57600;
    float* sTc  = sm + 57648;
    float* sNrm = sm + 57696;
    float* sRs  = sW1d;          // Rs staged here until weights overwrite

    const int tid  = threadIdx.x;
    const int wid  = tid >> 5;
    const int lane = tid & 31;
    const int blk  = blockIdx.x;
    const int t0   = blk * TT;

    // ---- phase 0: stage Rs + train tiles (t-major, q-scaled, zero-padded) ----
    for (int i = tid; i < M_MOL * NA * 3; i += NTHR) sRs[i] = Rs[i];
    for (int t = wid; t < TT; t += 24) {
        const float4* src = (const float4*)(xst + (size_t)(t0 + t) * P);
        const float4* srj = (const float4*)(Jx  + (size_t)(t0 + t) * P);
        float4* dx = (float4*)(sX + t * PPAD);
        float4* dj = (float4*)(sJ + t * PPAD);
        for (int c = lane; c < 72; c += 32) {
            float4 v, w;
            if (c < 69) { v = src[c]; w = srj[c]; }
            else        { v = make_float4(0.f,0.f,0.f,0.f); w = v; }
            v.x *= QC; v.y *= QC; v.z *= QC; v.w *= QC;
            dx[c] = v; dj[c] = w;
        }
    }
    __syncthreads();

    // ---- phase 1: qxs descriptors + per-t stats ----
    for (int idx = tid; idx < P * M_MOL; idx += NTHR) {
        int p = idx >> 6;
        int m = idx & 63;
        int i = (int)(0.5f * (1.0f + sqrtf(8.0f * (float)p + 1.0f)));
        while (i * (i - 1) / 2 > p) i--;
        while ((i + 1) * i / 2 <= p) i++;
        int j = p - i * (i - 1) / 2;
        const float* a = sRs + (m * NA + i) * 3;
        const float* b = sRs + (m * NA + j) * 3;
        float dx = a[0] - b[0], dy = a[1] - b[1], dz = a[2] - b[2];
        float r2 = dx * dx + dy * dy + dz * dz;
        sQx[p * M_MOL + m] = QC * rsqrtf(r2);
    }
    {
        #pragma unroll
        for (int k = 0; k < 2; k++) {
            int t = wid * 2 + k;
            const float* xr = sX + t * PPAD;
            const float* jr = sJ + t * PPAD;
            float tn = 0.0f, tc = 0.0f;
            for (int c = lane; c < PPAD; c += 32) {
                float x = xr[c];
                tn = fmaf(x, x, tn);
                tc = fmaf(x, jr[c], tc);
            }
            #pragma unroll
            for (int o = 16; o; o >>= 1) {
                tn += __shfl_down_sync(0xffffffffu, tn, o);
                tc += __shfl_down_sync(0xffffffffu, tc, o);
            }
            if (lane == 0) { sTn[t] = tn; sTc[t] = tc; }
        }
    }
    __syncthreads();

    // ---- phase 2: |qxs_m|^2 ----
    if (tid < M_MOL) {
        float s = 0.0f;
        #pragma unroll 4
        for (int p = 0; p < P; p++) {
            float v = sQx[p * M_MOL + tid];
            s = fmaf(v, v, s);
        }
        sNrm[tid] = s;
    }
    __syncthreads();

    // ---- phase 3: dual GEMM A, 8m x 1t per thread, p-range split in half ----
    const int ty  = tid & 7;          // m8 group
    const int txx = tid >> 3;         // 0..95
    const int tA  = txx >> 1;         // t index 0..47
    const int ph  = txx & 1;          // p-half
    const int m8  = ty * 8;
    const int ps  = ph * PHALF;

    u64 g1[4] = {0,0,0,0}, g2[4] = {0,0,0,0};
    {
        const float* xr = sX + tA * PPAD;
        const float* jr = sJ + tA * PPAD;
        #pragma unroll 2
        for (int p = ps; p < ps + PHALF; p++) {
            ulonglong2 a0 = *(const ulonglong2*)(sQx + p * M_MOL + m8);
            ulonglong2 a1 = *(const ulonglong2*)(sQx + p * M_MOL + m8 + 4);
            float xv = xr[p], jv = jr[p];
            u64 X = pk2(xv, xv), J = pk2(jv, jv);
            g1[0] = fma2(a0.x, X, g1[0]);
            g1[1] = fma2(a0.y, X, g1[1]);
            g1[2] = fma2(a1.x, X, g1[2]);
            g1[3] = fma2(a1.y, X, g1[3]);
            g2[0] = fma2(a0.x, J, g2[0]);
            g2[1] = fma2(a0.y, J, g2[1]);
            g2[2] = fma2(a1.x, J, g2[2]);
            g2[3] = fma2(a1.y, J, g2[3]);
        }
    }
    __syncthreads();            // all phase-3 reads of sQx done

    // ---- phase 4a: half-0 partials to smem (overwrites sQx head) ----
    if (ph == 0) {
        #pragma unroll
        for (int k = 0; k < 4; k++) {
            *(u64*)&sG1[tA * M_MOL + m8 + 2 * k] = g1[k];
            *(u64*)&sG2[tA * M_MOL + m8 + 2 * k] = g2[k];
        }
    }
    __syncthreads();

    // ---- phase 4b: half-1 combines + computes weights for its 8 m ----
    if (ph == 1) {
        float tn = sTn[tA], tc = sTc[tA];
        #pragma unroll
        for (int k = 0; k < 4; k++) {
            float lo1, hi1, lo2, hi2;
            upk2(g1[k], lo1, hi1);
            upk2(g2[k], lo2, hi2);
            #pragma unroll
            for (int h = 0; h < 2; h++) {
                int m = m8 + 2 * k + h;
                float G1 = (h ? hi1 : lo1) + sG1[tA * M_MOL + m];
                float G2 = (h ? hi2 : lo2) + sG2[tA * M_MOL + m];
                float d2   = fmaf(-2.0f, G1, sNrm[m] + tn);
                float dist = sqrtf(fmaxf(d2, 0.0f));
                float e    = C0 * __expf(-dist);
                float dot  = G2 - tc;
                float w1   = e * dot;
                float w2   = fmaf(e, dist, e);
                *(u64*)&sW1d[tA * 128 + 2 * m] = pk2(w1, w1);
                sW2 [tA * M_MOL + m] = w2;
                sDot[tA * M_MOL + m] = dot;
            }
        }
    }
    __syncthreads();

    // ---- phase 5a: deterministic per-block S1/Es partials ----
    if (tid < M_MOL) {
        float s1 = 0.0f, es = 0.0f;
        #pragma unroll 8
        for (int t = 0; t < TT; t++) {
            s1 += sW1d[t * 128 + 2 * tid];
            es  = fmaf(sW2[t * M_MOL + tid], sDot[t * M_MOL + tid], es);
        }
        g_S1part[blk * M_MOL + tid] = s1;
        g_Espart[blk * M_MOL + tid] = es;
    }

    // ---- phase 5b: GEMM B, 2m x 12p per thread (f32x2 over p-pairs) ----
    const int m0 = (tid & 31) * 2;
    const int pg = tid >> 5;          // 0..23 (pg 23 computes padding, discarded)
    const int p0 = pg * 12;
    u64 acc[2][6];
    #pragma unroll
    for (int mi = 0; mi < 2; mi++)
        #pragma unroll
        for (int pp = 0; pp < 6; pp++) acc[mi][pp] = 0ull;

    #pragma unroll 2
    for (int t = 0; t < TT; t++) {
        u64 w1a = *(const u64*)&sW1d[t * 128 + 2 * m0];
        u64 w1b = *(const u64*)&sW1d[t * 128 + 2 * m0 + 2];
        float2 w2f = *(const float2*)&sW2[t * M_MOL + m0];
        u64 w2a = pk2(w2f.x, w2f.x);
        u64 w2b = pk2(w2f.y, w2f.y);
        const float* xb = sX + t * PPAD + p0;
        const float* jb = sJ + t * PPAD + p0;
        #pragma unroll
        for (int c = 0; c < 3; c++) {
            ulonglong2 xc = *(const ulonglong2*)(xb + 4 * c);
            ulonglong2 jc = *(const ulonglong2*)(jb + 4 * c);
            acc[0][2*c]   = fma2(w1a, xc.x, fma2(w2a, jc.x, acc[0][2*c]));
            acc[0][2*c+1] = fma2(w1a, xc.y, fma2(w2a, jc.y, acc[0][2*c+1]));
            acc[1][2*c]   = fma2(w1b, xc.x, fma2(w2b, jc.x, acc[1][2*c]));
            acc[1][2*c+1] = fma2(w1b, xc.y, fma2(w2b, jc.y, acc[1][2*c+1]));
        }
    }
    __syncthreads();

    // ---- phase 6: stage acc -> smem -> coalesced global write ----
    float* sAcc = sm;   // sX/sJ region now dead (17664 < 27648)
    if (pg < 23) {
        #pragma unroll
        for (int mi = 0; mi < 2; mi++)
            #pragma unroll
            for (int pp = 0; pp < 6; pp++)
                *(u64*)&sAcc[(m0 + mi) * P + p0 + 2 * pp] = acc[mi][pp];
    }
    __syncthreads();
    {
        float* gA = g_Apart + (size_t)blk * M_MOL * P;
        #pragma unroll 4
        for (int idx = tid; idx < M_MOL * P; idx += NTHR) gA[idx] = sAcc[idx];
    }

    // ---- grid barrier (sense-reversal; 125 blocks co-resident) ----
    __threadfence();
    __syncthreads();
    if (tid == 0) {
        unsigned my = *(volatile unsigned*)&g_phase;
        int old = atomicAdd(&g_cnt, 1);
        if (old == NBLK - 1) {
            g_cnt = 0;
            __threadfence();
            atomicAdd(&g_phase, 1u);
        } else if (blk < M_MOL) {
            while (*(volatile unsigned*)&g_phase == my) __nanosleep(32);
        }
        __threadfence();
    }
    __syncthreads();
    if (blk >= M_MOL) return;

    // ---- post: reduce partials, Fs and Es for m = blk ----
    {
        const int m = blk;
        float* sFsx = sm;            // [276]
        float* sP   = sm + 512;      // [2][276]
        // b-split partial sums of A
        if (tid < 2 * P) {
            int h = tid / P;
            int p = tid - h * P;
            int b0 = h ? 63 : 0;
            int b1 = h ? NBLK : 63;
            float a = 0.0f;
            #pragma unroll 7
            for (int b = b0; b < b1; b++)
                a += g_Apart[((size_t)b * M_MOL + m) * P + p];
            sP[h * P + p] = a;
        }
        // scalar warp: S1, Es
        if (wid == 18) {
            float s1 = 0.0f, es = 0.0f;
            for (int b = lane; b < NBLK; b += 32) {
                s1 += g_S1part[b * M_MOL + m];
                es += g_Espart[b * M_MOL + m];
            }
            #pragma unroll
            for (int o = 16; o; o >>= 1) {
                s1 += __shfl_down_sync(0xffffffffu, s1, o);
                es += __shfl_down_sync(0xffffffffu, es, o);
            }
            if (lane == 0) {
                sm[1100] = s1;
                out[m] = es * (1.0f / QC);
            }
        }
        __syncthreads();
        if (tid < P) {
            int p = tid;
            int i = (int)(0.5f * (1.0f + sqrtf(8.0f * (float)p + 1.0f)));
            while (i * (i - 1) / 2 > p) i--;
            while ((i + 1) * i / 2 <= p) i++;
            int j = p - i * (i - 1) / 2;
            const float* a = Rs + (m * NA + i) * 3;
            const float* b = Rs + (m * NA + j) * 3;
            float dx = a[0] - b[0], dy = a[1] - b[1], dz = a[2] - b[2];
            float r2 = dx * dx + dy * dy + dz * dz;
            float xs = rsqrtf(r2);
            float qx = QC * xs;
            float asum = sP[p] + sP[P + p];
            sFsx[p] = (qx * sm[1100] - asum) * xs * xs * xs;
        }
        __syncthreads();
        if (tid < NA * 3) {
            int atom = tid / 3, d = tid % 3;
            float ra = Rs[(m * NA + atom) * 3 + d];
            float f = 0.0f;
            #pragma unroll
            for (int b = 0; b < NA; b++) {
                if (b == atom) continue;
                int hi = (atom > b) ? atom : b;
                int lo = (atom > b) ? b : atom;
                int pi = hi * (hi - 1) / 2 + lo;
                f = fmaf(Rs[(m * NA + b) * 3 + d] - ra, sFsx[pi], f);
            }
            out[M_MOL + (m * NA + atom) * 3 + d] = f;
        }
    }
}

// ---------------- entry ----------------
extern "C" void kernel_launch(void* const* d_in, const int* in_sizes, int n_in,
                              void* d_out, int out_size) {
    const float* Rs  = (const float*)d_in[0];
    const float* xst = (const float*)d_in[1];
    const float* Jx  = (const float*)d_in[2];
    float* out = (float*)d_out;

    cudaFuncSetAttribute(k_all, cudaFuncAttributeMaxDynamicSharedMemorySize, SMEM_BYTES);
    k_all<<<NBLK, NTHR, SMEM_BYTES>>>(Rs, xst, Jx, out);
}

// round 8
// speedup vs baseline: 1.2216x; 1.2216x over previous
#include <cuda_runtime.h>

#define M_MOL 64
#define NA    24
#define P     276
#define TT    48
#define NBLK  125
#define NTHR  768
#define QC    0.22360679774997896f   // sqrt(5)/sig, sig=10
#define C0    0.0166666666666667f    // 5/(3*sig^2)
#define PPAD  292                    // ≡0 mod 4 (float4-aligned), ≡4 mod 32 (bank-safe)

// ---------------- global scratch ----------------
__device__ float g_Apart [NBLK * M_MOL * P];
__device__ float g_S1part[NBLK * M_MOL];
__device__ float g_Espart[NBLK * M_MOL];
__device__ unsigned g_phase;   // zero-init, monotonic across replays
__device__ int      g_cnt;     // returns to 0 each call

// ---------------- f32x2 helpers ----------------
typedef unsigned long long u64;
__device__ __forceinline__ u64 pk2(float lo, float hi) {
    u64 r; asm("mov.b64 %0, {%1,%2};" : "=l"(r) : "f"(lo), "f"(hi)); return r;
}
__device__ __forceinline__ u64 fma2(u64 a, u64 b, u64 c) {
    u64 d; asm("fma.rn.f32x2 %0, %1, %2, %3;" : "=l"(d) : "l"(a), "l"(b), "l"(c)); return d;
}
__device__ __forceinline__ void upk2(u64 v, float& lo, float& hi) {
    asm("mov.b64 {%0,%1}, %2;" : "=f"(lo), "=f"(hi) : "l"(v));
}

// smem layout (floats):
//  sX   @0      [48][292]   14016
//  sJ   @14016  [48][292]   14016
//  sQx  @28032  [276][64]   17664  (sG1/sG2 alias after phase A)
//  sW1d @45696  [48][128]    6144  (sRs aliases here before weights)
//  sW2  @51840  [48][64]     3072
//  sS1p @54912  [12][64]      768
//  sEsp @55680  [12][64]      768
//  sTn  @56448  [48]
//  sTc  @56496  [48]
//  sNrm @56544  [64]   -> 56608 floats = 226432 B
#define OFF_J   14016
#define OFF_QX  28032
#define OFF_G1  28032
#define OFF_G2  31104
#define OFF_W1D 45696
#define OFF_W2  51840
#define OFF_S1P 54912
#define OFF_ESP 55680
#define OFF_TN  56448
#define OFF_TC  56496
#define OFF_NRM 56544
#define SMEM_FLOATS 56608
#define SMEM_BYTES  (SMEM_FLOATS * 4)

__global__ __launch_bounds__(NTHR, 1)
void k_all(const float* __restrict__ Rs, const float* __restrict__ xst,
           const float* __restrict__ Jx, float* __restrict__ out) {
    extern __shared__ float sm[];
    float* sX   = sm;
    float* sJ   = sm + OFF_J;
    float* sQx  = sm + OFF_QX;
    float* sG1  = sm + OFF_G1;
    float* sG2  = sm + OFF_G2;
    float* sW1d = sm + OFF_W1D;
    float* sW2  = sm + OFF_W2;
    float* sS1p = sm + OFF_S1P;
    float* sEsp = sm + OFF_ESP;
    float* sTn  = sm + OFF_TN;
    float* sTc  = sm + OFF_TC;
    float* sNrm = sm + OFF_NRM;
    float* sRs  = sW1d;          // Rs staged here until weights overwrite

    const int tid  = threadIdx.x;
    const int wid  = tid >> 5;
    const int lane = tid & 31;
    const int blk  = blockIdx.x;
    const int t0   = blk * TT;

    // ---- phase 0: stage Rs + train tiles (t-major, q-scaled, cols 276..287 zero) ----
    for (int i = tid; i < M_MOL * NA * 3; i += NTHR) sRs[i] = Rs[i];
    #pragma unroll
    for (int k = 0; k < 2; k++) {
        int t = wid + 24 * k;
        const float4* src = (const float4*)(xst + (size_t)(t0 + t) * P);
        const float4* srj = (const float4*)(Jx  + (size_t)(t0 + t) * P);
        float* dx = sX + t * PPAD;
        float* dj = sJ + t * PPAD;
        for (int c = lane; c < 72; c += 32) {
            float4 v, w;
            if (c < 69) { v = src[c]; w = srj[c]; }
            else        { v = make_float4(0.f,0.f,0.f,0.f); w = v; }
            v.x *= QC; v.y *= QC; v.z *= QC; v.w *= QC;
            *(float4*)(dx + 4 * c) = v;
            *(float4*)(dj + 4 * c) = w;
        }
    }
    __syncthreads();

    // ---- phase 1: qxs descriptors + per-t stats ----
    for (int idx = tid; idx < P * M_MOL; idx += NTHR) {
        int p = idx >> 6;
        int m = idx & 63;
        int i = (int)(0.5f * (1.0f + sqrtf(8.0f * (float)p + 1.0f)));
        while (i * (i - 1) / 2 > p) i--;
        while ((i + 1) * i / 2 <= p) i++;
        int j = p - i * (i - 1) / 2;
        const float* a = sRs + (m * NA + i) * 3;
        const float* b = sRs + (m * NA + j) * 3;
        float dx = a[0] - b[0], dy = a[1] - b[1], dz = a[2] - b[2];
        float r2 = dx * dx + dy * dy + dz * dz;
        sQx[p * M_MOL + m] = QC * rsqrtf(r2);
    }
    #pragma unroll
    for (int k = 0; k < 2; k++) {
        int t = wid * 2 + k;
        const float* xr = sX + t * PPAD;
        const float* jr = sJ + t * PPAD;
        float tn = 0.0f, tc = 0.0f;
        #pragma unroll
        for (int c = lane; c < 288; c += 32) {
            float x = xr[c];
            tn = fmaf(x, x, tn);
            tc = fmaf(x, jr[c], tc);
        }
        #pragma unroll
        for (int o = 16; o; o >>= 1) {
            tn += __shfl_down_sync(0xffffffffu, tn, o);
            tc += __shfl_down_sync(0xffffffffu, tc, o);
        }
        if (lane == 0) { sTn[t] = tn; sTc[t] = tc; }
    }
    __syncthreads();

    // ---- phase 2: |qxs_m|^2 ----
    if (tid < M_MOL) {
        float s = 0.0f;
        #pragma unroll 4
        for (int p = 0; p < P; p++) {
            float v = sQx[p * M_MOL + tid];
            s = fmaf(v, v, s);
        }
        sNrm[tid] = s;
    }
    __syncthreads();

    // ---- phase A: dual GEMM, warp-uniform p-half, interleaved m-octet ----
    const int ph = wid / 12;          // p-half, uniform per warp
    const int tw = wid % 12;
    const int ty = lane & 7;
    const int tt = lane >> 3;
    const int tA = tw * 4 + tt;       // t index 0..47
    const int mo = 4 * ty;            // m-octet: {mo..mo+3} U {32+mo..32+mo+3}

    u64 g1[4] = {0,0,0,0}, g2[4] = {0,0,0,0};
    {
        const float* xr = sX + tA * PPAD;
        const float* jr = sJ + tA * PPAD;
        const int ps = ph * 138;
        #pragma unroll 2
        for (int p = ps; p < ps + 138; p++) {
            ulonglong2 a0 = *(const ulonglong2*)(sQx + p * M_MOL + mo);
            ulonglong2 a1 = *(const ulonglong2*)(sQx + p * M_MOL + 32 + mo);
            float xv = xr[p], jv = jr[p];
            u64 X = pk2(xv, xv), J = pk2(jv, jv);
            g1[0] = fma2(a0.x, X, g1[0]);
            g1[1] = fma2(a0.y, X, g1[1]);
            g1[2] = fma2(a1.x, X, g1[2]);
            g1[3] = fma2(a1.y, X, g1[3]);
            g2[0] = fma2(a0.x, J, g2[0]);
            g2[1] = fma2(a0.y, J, g2[1]);
            g2[2] = fma2(a1.x, J, g2[2]);
            g2[3] = fma2(a1.y, J, g2[3]);
        }
    }
    __syncthreads();                  // sQx reads complete

    // ---- half-0 writes partials (aliases sQx head) ----
    if (ph == 0) {
        ulonglong2 v;
        v.x = g1[0]; v.y = g1[1];
        *(ulonglong2*)&sG1[tA * M_MOL + mo] = v;
        v.x = g1[2]; v.y = g1[3];
        *(ulonglong2*)&sG1[tA * M_MOL + 32 + mo] = v;
        v.x = g2[0]; v.y = g2[1];
        *(ulonglong2*)&sG2[tA * M_MOL + mo] = v;
        v.x = g2[2]; v.y = g2[3];
        *(ulonglong2*)&sG2[tA * M_MOL + 32 + mo] = v;
    }
    __syncthreads();

    // ---- half-1 combines + weights + in-warp S1/Es partials ----
    if (ph == 1) {
        float4 o1a = *(const float4*)&sG1[tA * M_MOL + mo];
        float4 o1b = *(const float4*)&sG1[tA * M_MOL + 32 + mo];
        float4 o2a = *(const float4*)&sG2[tA * M_MOL + mo];
        float4 o2b = *(const float4*)&sG2[tA * M_MOL + 32 + mo];
        float G1v[8], G2v[8];
        upk2(g1[0], G1v[0], G1v[1]); upk2(g1[1], G1v[2], G1v[3]);
        upk2(g1[2], G1v[4], G1v[5]); upk2(g1[3], G1v[6], G1v[7]);
        upk2(g2[0], G2v[0], G2v[1]); upk2(g2[1], G2v[2], G2v[3]);
        upk2(g2[2], G2v[4], G2v[5]); upk2(g2[3], G2v[6], G2v[7]);
        G1v[0] += o1a.x; G1v[1] += o1a.y; G1v[2] += o1a.z; G1v[3] += o1a.w;
        G1v[4] += o1b.x; G1v[5] += o1b.y; G1v[6] += o1b.z; G1v[7] += o1b.w;
        G2v[0] += o2a.x; G2v[1] += o2a.y; G2v[2] += o2a.z; G2v[3] += o2a.w;
        G2v[4] += o2b.x; G2v[5] += o2b.y; G2v[6] += o2b.z; G2v[7] += o2b.w;

        float tn = sTn[tA], tc = sTc[tA];
        float s1m[8], esm[8];
        #pragma unroll
        for (int k = 0; k < 8; k++) {
            int m = (k < 4) ? (mo + k) : (32 + mo + k - 4);
            float d2   = fmaf(-2.0f, G1v[k], sNrm[m] + tn);
            float dist = sqrtf(fmaxf(d2, 0.0f));
            float e    = C0 * __expf(-dist);
            float dot  = G2v[k] - tc;
            float w1   = e * dot;
            float w2   = fmaf(e, dist, e);
            *(u64*)&sW1d[tA * 128 + 2 * m] = pk2(w1, w1);
            sW2[tA * M_MOL + m] = w2;
            s1m[k] = w1;
            esm[k] = w2 * dot;
        }
        #pragma unroll
        for (int k = 0; k < 8; k++) {
            s1m[k] += __shfl_xor_sync(0xffffffffu, s1m[k], 8);
            s1m[k] += __shfl_xor_sync(0xffffffffu, s1m[k], 16);
            esm[k] += __shfl_xor_sync(0xffffffffu, esm[k], 8);
            esm[k] += __shfl_xor_sync(0xffffffffu, esm[k], 16);
        }
        if (tt == 0) {
            #pragma unroll
            for (int k = 0; k < 8; k++) {
                int m = (k < 4) ? (mo + k) : (32 + mo + k - 4);
                sS1p[tw * M_MOL + m] = s1m[k];
                sEsp[tw * M_MOL + m] = esm[k];
            }
        }
    }
    __syncthreads();

    // ---- S1/Es per-block partials to global ----
    if (tid < M_MOL) {
        float s1 = 0.0f, es = 0.0f;
        #pragma unroll
        for (int q = 0; q < 12; q++) {
            s1 += sS1p[q * M_MOL + tid];
            es += sEsp[q * M_MOL + tid];
        }
        g_S1part[blk * M_MOL + tid] = s1;
        g_Espart[blk * M_MOL + tid] = es;
    }

    // ---- phase B: A[m,p] = sum_t (w1*qxst + w2*Jx); lanes span p, w uniform ----
    const int g8  = wid & 7;          // m-octet group
    const int pt  = wid >> 3;         // p-third 0..2
    const int p0  = pt * 96;
    const int mo2 = 4 * g8;
    const int pA  = p0 + 2 * lane;               // slot 0 p-pair
    const int pBr = p0 + 64 + 2 * lane;          // slot 1 p-pair (raw)
    const bool st1 = (pBr + 1) < P;              // slot-1 validity
    const int pB  = st1 ? pBr : 274;             // clamped (in-bounds, result discarded)
    u64 acc[8][2];
    #pragma unroll
    for (int k = 0; k < 8; k++) { acc[k][0] = 0ull; acc[k][1] = 0ull; }

    #pragma unroll 2
    for (int t = 0; t < TT; t++) {
        const float* xrow = sX + t * PPAD;
        const float* jrow = sJ + t * PPAD;
        u64 x0 = *(const u64*)(xrow + pA);
        u64 j0 = *(const u64*)(jrow + pA);
        u64 x1 = *(const u64*)(xrow + pB);
        u64 j1 = *(const u64*)(jrow + pB);
        {
            ulonglong2 w1a = *(const ulonglong2*)&sW1d[t * 128 + 8 * g8];
            ulonglong2 w1b = *(const ulonglong2*)&sW1d[t * 128 + 8 * g8 + 4];
            float4 w2q = *(const float4*)&sW2[t * M_MOL + mo2];
            u64 w2p0 = pk2(w2q.x, w2q.x), w2p1 = pk2(w2q.y, w2q.y);
            u64 w2p2 = pk2(w2q.z, w2q.z), w2p3 = pk2(w2q.w, w2q.w);
            acc[0][0] = fma2(w1a.x, x0, fma2(w2p0, j0, acc[0][0]));
            acc[1][0] = fma2(w1a.y, x0, fma2(w2p1, j0, acc[1][0]));
            acc[2][0] = fma2(w1b.x, x0, fma2(w2p2, j0, acc[2][0]));
            acc[3][0] = fma2(w1b.y, x0, fma2(w2p3, j0, acc[3][0]));
            acc[0][1] = fma2(w1a.x, x1, fma2(w2p0, j1, acc[0][1]));
            acc[1][1] = fma2(w1a.y, x1, fma2(w2p1, j1, acc[1][1]));
            acc[2][1] = fma2(w1b.x, x1, fma2(w2p2, j1, acc[2][1]));
            acc[3][1] = fma2(w1b.y, x1, fma2(w2p3, j1, acc[3][1]));
        }
        {
            ulonglong2 w1a = *(const ulonglong2*)&sW1d[t * 128 + 64 + 8 * g8];
            ulonglong2 w1b = *(const ulonglong2*)&sW1d[t * 128 + 64 + 8 * g8 + 4];
            float4 w2q = *(const float4*)&sW2[t * M_MOL + 32 + mo2];
            u64 w2p0 = pk2(w2q.x, w2q.x), w2p1 = pk2(w2q.y, w2q.y);
            u64 w2p2 = pk2(w2q.z, w2q.z), w2p3 = pk2(w2q.w, w2q.w);
            acc[4][0] = fma2(w1a.x, x0, fma2(w2p0, j0, acc[4][0]));
            acc[5][0] = fma2(w1a.y, x0, fma2(w2p1, j0, acc[5][0]));
            acc[6][0] = fma2(w1b.x, x0, fma2(w2p2, j0, acc[6][0]));
            acc[7][0] = fma2(w1b.y, x0, fma2(w2p3, j0, acc[7][0]));
            acc[4][1] = fma2(w1a.x, x1, fma2(w2p0, j1, acc[4][1]));
            acc[5][1] = fma2(w1a.y, x1, fma2(w2p1, j1, acc[5][1]));
            acc[6][1] = fma2(w1b.x, x1, fma2(w2p2, j1, acc[6][1]));
            acc[7][1] = fma2(w1b.y, x1, fma2(w2p3, j1, acc[7][1]));
        }
    }
    __syncthreads();

    // ---- stage acc -> smem (sX region dead) -> coalesced global write ----
    float* sAcc = sm;                 // [64][276]
    #pragma unroll
    for (int k = 0; k < 8; k++) {
        int m = (k < 4) ? (mo2 + k) : (32 + mo2 + k - 4);
        *(u64*)&sAcc[m * P + pA] = acc[k][0];
        if (st1) *(u64*)&sAcc[m * P + pBr] = acc[k][1];
    }
    __syncthreads();
    {
        float* gA = g_Apart + (size_t)blk * M_MOL * P;
        #pragma unroll 4
        for (int idx = tid; idx < M_MOL * P; idx += NTHR) gA[idx] = sAcc[idx];
    }

    // ---- grid barrier (125 blocks co-resident) ----
    __threadfence();
    __syncthreads();
    if (tid == 0) {
        unsigned my = *(volatile unsigned*)&g_phase;
        int old = atomicAdd(&g_cnt, 1);
        if (old == NBLK - 1) {
            g_cnt = 0;
            __threadfence();
            atomicAdd(&g_phase, 1u);
        } else if (blk < M_MOL) {
            while (*(volatile unsigned*)&g_phase == my) __nanosleep(32);
        }
        __threadfence();
    }
    __syncthreads();
    if (blk >= M_MOL) return;

    // ---- post: reduce partials, Fs and Es for m = blk ----
    {
        const int m = blk;
        float* sFsx = sm;            // [276]
        float* sP   = sm + 512;      // [2][276]
        if (tid < 2 * P) {
            int h = tid / P;
            int p = tid - h * P;
            int b0 = h ? 63 : 0;
            int b1 = h ? NBLK : 63;
            float a = 0.0f;
            #pragma unroll 7
            for (int b = b0; b < b1; b++)
                a += g_Apart[((size_t)b * M_MOL + m) * P + p];
            sP[h * P + p] = a;
        }
        if (wid == 18) {
            float s1 = 0.0f, es = 0.0f;
            for (int b = lane; b < NBLK; b += 32) {
                s1 += g_S1part[b * M_MOL + m];
                es += g_Espart[b * M_MOL + m];
            }
            #pragma unroll
            for (int o = 16; o; o >>= 1) {
                s1 += __shfl_down_sync(0xffffffffu, s1, o);
                es += __shfl_down_sync(0xffffffffu, es, o);
            }
            if (lane == 0) {
                sm[1100] = s1;
                out[m] = es * (1.0f / QC);
            }
        }
        __syncthreads();
        if (tid < P) {
            int p = tid;
            int i = (int)(0.5f * (1.0f + sqrtf(8.0f * (float)p + 1.0f)));
            while (i * (i - 1) / 2 > p) i--;
            while ((i + 1) * i / 2 <= p) i++;
            int j = p - i * (i - 1) / 2;
            const float* a = Rs + (m * NA + i) * 3;
            const float* b = Rs + (m * NA + j) * 3;
            float dx = a[0] - b[0], dy = a[1] - b[1], dz = a[2] - b[2];
            float r2 = dx * dx + dy * dy + dz * dz;
            float xs = rsqrtf(r2);
            float qx = QC * xs;
            float asum = sP[p] + sP[P + p];
            sFsx[p] = (qx * sm[1100] - asum) * xs * xs * xs;
        }
        __syncthreads();
        if (tid < NA * 3) {
            int atom = tid / 3, d = tid % 3;
            float ra = Rs[(m * NA + atom) * 3 + d];
            float f = 0.0f;
            #pragma unroll
            for (int b = 0; b < NA; b++) {
                if (b == atom) continue;
                int hi = (atom > b) ? atom : b;
                int lo = (atom > b) ? b : atom;
                int pi = hi * (hi - 1) / 2 + lo;
                f = fmaf(Rs[(m * NA + b) * 3 + d] - ra, sFsx[pi], f);
            }
            out[M_MOL + (m * NA + atom) * 3 + d] = f;
        }
    }
}

// ---------------- entry ----------------
extern "C" void kernel_launch(void* const* d_in, const int* in_sizes, int n_in,
                              void* d_out, int out_size) {
    const float* Rs  = (const float*)d_in[0];
    const float* xst = (const float*)d_in[1];
    const float* Jx  = (const float*)d_in[2];
    float* out = (float*)d_out;

    cudaFuncSetAttribute(k_all, cudaFuncAttributeMaxDynamicSharedMemorySize, SMEM_BYTES);
    k_all<<<NBLK, NTHR, SMEM_BYTES>>>(Rs, xst, Jx, out);
}

// round 9
// speedup vs baseline: 1.2636x; 1.0344x over previous
#include <cuda_runtime.h>

#define M_MOL 64
#define NA    24
#define P     276
#define TT    48
#define NBLK  125
#define NTHR  768
#define QC    0.22360679774997896f   // sqrt(5)/sig, sig=10
#define C0    0.0166666666666667f    // 5/(3*sig^2)
#define PPAD  292                    // ≡0 mod 4 (float4-aligned), ≡4 mod 32 (bank-safe)

// ---------------- global scratch ----------------
__device__ float g_Apart [NBLK * M_MOL * P];
__device__ float g_S1part[NBLK * M_MOL];
__device__ float g_Espart[NBLK * M_MOL];
__device__ unsigned g_phase;   // zero-init, monotonic across replays
__device__ int      g_cnt;     // returns to 0 each call

// ---------------- f32x2 helpers ----------------
typedef unsigned long long u64;
__device__ __forceinline__ u64 pk2(float lo, float hi) {
    u64 r; asm("mov.b64 %0, {%1,%2};" : "=l"(r) : "f"(lo), "f"(hi)); return r;
}
__device__ __forceinline__ u64 fma2(u64 a, u64 b, u64 c) {
    u64 d; asm("fma.rn.f32x2 %0, %1, %2, %3;" : "=l"(d) : "l"(a), "l"(b), "l"(c)); return d;
}
__device__ __forceinline__ void upk2(u64 v, float& lo, float& hi) {
    asm("mov.b64 {%0,%1}, %2;" : "=f"(lo), "=f"(hi) : "l"(v));
}

// smem layout (floats): identical to R8
#define OFF_J   14016
#define OFF_QX  28032
#define OFF_G1  28032
#define OFF_G2  31104
#define OFF_W1D 45696
#define OFF_W2  51840
#define OFF_S1P 54912
#define OFF_ESP 55680
#define OFF_TN  56448
#define OFF_TC  56496
#define OFF_NRM 56544
#define SMEM_FLOATS 56608
#define SMEM_BYTES  (SMEM_FLOATS * 4)

__global__ __launch_bounds__(NTHR, 1)
void k_all(const float* __restrict__ Rs, const float* __restrict__ xst,
           const float* __restrict__ Jx, float* __restrict__ out) {
    extern __shared__ float sm[];
    float* sX   = sm;
    float* sJ   = sm + OFF_J;
    float* sQx  = sm + OFF_QX;
    float* sG1  = sm + OFF_G1;
    float* sG2  = sm + OFF_G2;
    float* sW1d = sm + OFF_W1D;
    float* sW2  = sm + OFF_W2;
    float* sS1p = sm + OFF_S1P;
    float* sEsp = sm + OFF_ESP;
    float* sTn  = sm + OFF_TN;
    float* sTc  = sm + OFF_TC;
    float* sNrm = sm + OFF_NRM;
    float* sRs  = sW1d;          // Rs staged here until weights overwrite

    const int tid  = threadIdx.x;
    const int wid  = tid >> 5;
    const int lane = tid & 31;
    const int blk  = blockIdx.x;
    const int t0   = blk * TT;

    // ---- phase 0: stage Rs + train tiles ----
    for (int i = tid; i < M_MOL * NA * 3; i += NTHR) sRs[i] = Rs[i];
    #pragma unroll
    for (int k = 0; k < 2; k++) {
        int t = wid + 24 * k;
        const float4* src = (const float4*)(xst + (size_t)(t0 + t) * P);
        const float4* srj = (const float4*)(Jx  + (size_t)(t0 + t) * P);
        float* dx = sX + t * PPAD;
        float* dj = sJ + t * PPAD;
        for (int c = lane; c < 72; c += 32) {
            float4 v, w;
            if (c < 69) { v = src[c]; w = srj[c]; }
            else        { v = make_float4(0.f,0.f,0.f,0.f); w = v; }
            v.x *= QC; v.y *= QC; v.z *= QC; v.w *= QC;
            *(float4*)(dx + 4 * c) = v;
            *(float4*)(dj + 4 * c) = w;
        }
    }
    __syncthreads();

    // ---- phase 1: qxs descriptors + per-t stats ----
    for (int idx = tid; idx < P * M_MOL; idx += NTHR) {
        int p = idx >> 6;
        int m = idx & 63;
        int i = (int)(0.5f * (1.0f + sqrtf(8.0f * (float)p + 1.0f)));
        while (i * (i - 1) / 2 > p) i--;
        while ((i + 1) * i / 2 <= p) i++;
        int j = p - i * (i - 1) / 2;
        const float* a = sRs + (m * NA + i) * 3;
        const float* b = sRs + (m * NA + j) * 3;
        float dx = a[0] - b[0], dy = a[1] - b[1], dz = a[2] - b[2];
        float r2 = dx * dx + dy * dy + dz * dz;
        sQx[p * M_MOL + m] = QC * rsqrtf(r2);
    }
    #pragma unroll
    for (int k = 0; k < 2; k++) {
        int t = wid * 2 + k;
        const float* xr = sX + t * PPAD;
        const float* jr = sJ + t * PPAD;
        float tn = 0.0f, tc = 0.0f;
        #pragma unroll
        for (int c = lane; c < 288; c += 32) {
            float x = xr[c];
            tn = fmaf(x, x, tn);
            tc = fmaf(x, jr[c], tc);
        }
        #pragma unroll
        for (int o = 16; o; o >>= 1) {
            tn += __shfl_down_sync(0xffffffffu, tn, o);
            tc += __shfl_down_sync(0xffffffffu, tc, o);
        }
        if (lane == 0) { sTn[t] = tn; sTc[t] = tc; }
    }
    __syncthreads();

    // ---- phase 2: |qxs_m|^2, all 768 threads (12 p-chunks x 64 m) ----
    {
        int m = tid & 63;
        int k = tid >> 6;            // 0..11
        int pbeg = k * 23;
        float s = 0.0f;
        #pragma unroll
        for (int p = pbeg; p < pbeg + 23; p++) {
            float v = sQx[p * M_MOL + m];
            s = fmaf(v, v, s);
        }
        sS1p[k * M_MOL + m] = s;     // sS1p free until weights phase
    }
    __syncthreads();
    if (tid < M_MOL) {
        float s = 0.0f;
        #pragma unroll
        for (int q = 0; q < 12; q++) s += sS1p[q * M_MOL + tid];
        sNrm[tid] = s;
    }
    __syncthreads();

    // ---- phase A: dual GEMM, software-pipelined (prefetch-1, p-pairs) ----
    const int ph = wid / 12;          // p-half, uniform per warp
    const int tw = wid % 12;
    const int ty = lane & 7;
    const int tt = lane >> 3;
    const int tA = tw * 4 + tt;       // t index 0..47
    const int mo = 4 * ty;            // m-octet: {mo..mo+3} U {32+mo..32+mo+3}
    const int ps = ph * 138;

    u64 g1[4] = {0,0,0,0}, g2[4] = {0,0,0,0};
    {
        const float* xr = sX + tA * PPAD;
        const float* jr = sJ + tA * PPAD;
        const float* qp = sQx + ps * M_MOL;
        ulonglong2 a0 = *(const ulonglong2*)(qp + mo);
        ulonglong2 a1 = *(const ulonglong2*)(qp + 32 + mo);
        ulonglong2 b0 = *(const ulonglong2*)(qp + 64 + mo);
        ulonglong2 b1 = *(const ulonglong2*)(qp + 96 + mo);
        float2 xv = *(const float2*)(xr + ps);
        float2 jv = *(const float2*)(jr + ps);
        #pragma unroll 4
        for (int it = 0; it < 68; it++) {
            int p = ps + 2 * it;
            const float* qn = sQx + (p + 2) * M_MOL;   // prefetch next pair
            ulonglong2 na0 = *(const ulonglong2*)(qn + mo);
            ulonglong2 na1 = *(const ulonglong2*)(qn + 32 + mo);
            ulonglong2 nb0 = *(const ulonglong2*)(qn + 64 + mo);
            ulonglong2 nb1 = *(const ulonglong2*)(qn + 96 + mo);
            float2 nxv = *(const float2*)(xr + p + 2);
            float2 njv = *(const float2*)(jr + p + 2);
            u64 X0 = pk2(xv.x, xv.x), J0 = pk2(jv.x, jv.x);
            u64 X1 = pk2(xv.y, xv.y), J1 = pk2(jv.y, jv.y);
            g1[0] = fma2(a0.x, X0, g1[0]);
            g1[1] = fma2(a0.y, X0, g1[1]);
            g1[2] = fma2(a1.x, X0, g1[2]);
            g1[3] = fma2(a1.y, X0, g1[3]);
            g2[0] = fma2(a0.x, J0, g2[0]);
            g2[1] = fma2(a0.y, J0, g2[1]);
            g2[2] = fma2(a1.x, J0, g2[2]);
            g2[3] = fma2(a1.y, J0, g2[3]);
            g1[0] = fma2(b0.x, X1, g1[0]);
            g1[1] = fma2(b0.y, X1, g1[1]);
            g1[2] = fma2(b1.x, X1, g1[2]);
            g1[3] = fma2(b1.y, X1, g1[3]);
            g2[0] = fma2(b0.x, J1, g2[0]);
            g2[1] = fma2(b0.y, J1, g2[1]);
            g2[2] = fma2(b1.x, J1, g2[2]);
            g2[3] = fma2(b1.y, J1, g2[3]);
            a0 = na0; a1 = na1; b0 = nb0; b1 = nb1; xv = nxv; jv = njv;
        }
        // final pair p = ps+136 (regs already loaded)
        {
            u64 X0 = pk2(xv.x, xv.x), J0 = pk2(jv.x, jv.x);
            u64 X1 = pk2(xv.y, xv.y), J1 = pk2(jv.y, jv.y);
            g1[0] = fma2(a0.x, X0, g1[0]);
            g1[1] = fma2(a0.y, X0, g1[1]);
            g1[2] = fma2(a1.x, X0, g1[2]);
            g1[3] = fma2(a1.y, X0, g1[3]);
            g2[0] = fma2(a0.x, J0, g2[0]);
            g2[1] = fma2(a0.y, J0, g2[1]);
            g2[2] = fma2(a1.x, J0, g2[2]);
            g2[3] = fma2(a1.y, J0, g2[3]);
            g1[0] = fma2(b0.x, X1, g1[0]);
            g1[1] = fma2(b0.y, X1, g1[1]);
            g1[2] = fma2(b1.x, X1, g1[2]);
            g1[3] = fma2(b1.y, X1, g1[3]);
            g2[0] = fma2(b0.x, J1, g2[0]);
            g2[1] = fma2(b0.y, J1, g2[1]);
            g2[2] = fma2(b1.x, J1, g2[2]);
            g2[3] = fma2(b1.y, J1, g2[3]);
        }
    }
    __syncthreads();                  // sQx reads complete

    // ---- half-0 writes partials (aliases sQx head) ----
    if (ph == 0) {
        ulonglong2 v;
        v.x = g1[0]; v.y = g1[1];
        *(ulonglong2*)&sG1[tA * M_MOL + mo] = v;
        v.x = g1[2]; v.y = g1[3];
        *(ulonglong2*)&sG1[tA * M_MOL + 32 + mo] = v;
        v.x = g2[0]; v.y = g2[1];
        *(ulonglong2*)&sG2[tA * M_MOL + mo] = v;
        v.x = g2[2]; v.y = g2[3];
        *(ulonglong2*)&sG2[tA * M_MOL + 32 + mo] = v;
    }
    __syncthreads();

    // ---- half-1 combines + weights + in-warp S1/Es partials ----
    if (ph == 1) {
        float4 o1a = *(const float4*)&sG1[tA * M_MOL + mo];
        float4 o1b = *(const float4*)&sG1[tA * M_MOL + 32 + mo];
        float4 o2a = *(const float4*)&sG2[tA * M_MOL + mo];
        float4 o2b = *(const float4*)&sG2[tA * M_MOL + 32 + mo];
        float G1v[8], G2v[8];
        upk2(g1[0], G1v[0], G1v[1]); upk2(g1[1], G1v[2], G1v[3]);
        upk2(g1[2], G1v[4], G1v[5]); upk2(g1[3], G1v[6], G1v[7]);
        upk2(g2[0], G2v[0], G2v[1]); upk2(g2[1], G2v[2], G2v[3]);
        upk2(g2[2], G2v[4], G2v[5]); upk2(g2[3], G2v[6], G2v[7]);
        G1v[0] += o1a.x; G1v[1] += o1a.y; G1v[2] += o1a.z; G1v[3] += o1a.w;
        G1v[4] += o1b.x; G1v[5] += o1b.y; G1v[6] += o1b.z; G1v[7] += o1b.w;
        G2v[0] += o2a.x; G2v[1] += o2a.y; G2v[2] += o2a.z; G2v[3] += o2a.w;
        G2v[4] += o2b.x; G2v[5] += o2b.y; G2v[6] += o2b.z; G2v[7] += o2b.w;

        float tn = sTn[tA], tc = sTc[tA];
        float s1m[8], esm[8];
        #pragma unroll
        for (int k = 0; k < 8; k++) {
            int m = (k < 4) ? (mo + k) : (32 + mo + k - 4);
            float d2   = fmaf(-2.0f, G1v[k], sNrm[m] + tn);
            float dist = sqrtf(fmaxf(d2, 0.0f));
            float e    = C0 * __expf(-dist);
            float dot  = G2v[k] - tc;
            float w1   = e * dot;
            float w2   = fmaf(e, dist, e);
            *(u64*)&sW1d[tA * 128 + 2 * m] = pk2(w1, w1);
            sW2[tA * M_MOL + m] = w2;
            s1m[k] = w1;
            esm[k] = w2 * dot;
        }
        #pragma unroll
        for (int k = 0; k < 8; k++) {
            s1m[k] += __shfl_xor_sync(0xffffffffu, s1m[k], 8);
            s1m[k] += __shfl_xor_sync(0xffffffffu, s1m[k], 16);
            esm[k] += __shfl_xor_sync(0xffffffffu, esm[k], 8);
            esm[k] += __shfl_xor_sync(0xffffffffu, esm[k], 16);
        }
        if (tt == 0) {
            #pragma unroll
            for (int k = 0; k < 8; k++) {
                int m = (k < 4) ? (mo + k) : (32 + mo + k - 4);
                sS1p[tw * M_MOL + m] = s1m[k];
                sEsp[tw * M_MOL + m] = esm[k];
            }
        }
    }
    __syncthreads();

    // ---- S1/Es per-block partials to global ----
    if (tid < M_MOL) {
        float s1 = 0.0f, es = 0.0f;
        #pragma unroll
        for (int q = 0; q < 12; q++) {
            s1 += sS1p[q * M_MOL + tid];
            es += sEsp[q * M_MOL + tid];
        }
        g_S1part[blk * M_MOL + tid] = s1;
        g_Espart[blk * M_MOL + tid] = es;
    }

    // ---- phase B: A[m,p] = sum_t (w1*qxst + w2*Jx) ----
    const int g8  = wid & 7;          // m-octet group
    const int pt  = wid >> 3;         // p-third 0..2
    const int p0  = pt * 96;
    const int mo2 = 4 * g8;
    const int pA  = p0 + 2 * lane;
    const int pBr = p0 + 64 + 2 * lane;
    const bool st1 = (pBr + 1) < P;
    const int pB  = st1 ? pBr : 274;
    u64 acc[8][2];
    #pragma unroll
    for (int k = 0; k < 8; k++) { acc[k][0] = 0ull; acc[k][1] = 0ull; }

    #pragma unroll 2
    for (int t = 0; t < TT; t++) {
        const float* xrow = sX + t * PPAD;
        const float* jrow = sJ + t * PPAD;
        u64 x0 = *(const u64*)(xrow + pA);
        u64 j0 = *(const u64*)(jrow + pA);
        u64 x1 = *(const u64*)(xrow + pB);
        u64 j1 = *(const u64*)(jrow + pB);
        {
            ulonglong2 w1a = *(const ulonglong2*)&sW1d[t * 128 + 8 * g8];
            ulonglong2 w1b = *(const ulonglong2*)&sW1d[t * 128 + 8 * g8 + 4];
            float4 w2q = *(const float4*)&sW2[t * M_MOL + mo2];
            u64 w2p0 = pk2(w2q.x, w2q.x), w2p1 = pk2(w2q.y, w2q.y);
            u64 w2p2 = pk2(w2q.z, w2q.z), w2p3 = pk2(w2q.w, w2q.w);
            acc[0][0] = fma2(w1a.x, x0, fma2(w2p0, j0, acc[0][0]));
            acc[1][0] = fma2(w1a.y, x0, fma2(w2p1, j0, acc[1][0]));
            acc[2][0] = fma2(w1b.x, x0, fma2(w2p2, j0, acc[2][0]));
            acc[3][0] = fma2(w1b.y, x0, fma2(w2p3, j0, acc[3][0]));
            acc[0][1] = fma2(w1a.x, x1, fma2(w2p0, j1, acc[0][1]));
            acc[1][1] = fma2(w1a.y, x1, fma2(w2p1, j1, acc[1][1]));
            acc[2][1] = fma2(w1b.x, x1, fma2(w2p2, j1, acc[2][1]));
            acc[3][1] = fma2(w1b.y, x1, fma2(w2p3, j1, acc[3][1]));
        }
        {
            ulonglong2 w1a = *(const ulonglong2*)&sW1d[t * 128 + 64 + 8 * g8];
            ulonglong2 w1b = *(const ulonglong2*)&sW1d[t * 128 + 64 + 8 * g8 + 4];
            float4 w2q = *(const float4*)&sW2[t * M_MOL + 32 + mo2];
            u64 w2p0 = pk2(w2q.x, w2q.x), w2p1 = pk2(w2q.y, w2q.y);
            u64 w2p2 = pk2(w2q.z, w2q.z), w2p3 = pk2(w2q.w, w2q.w);
            acc[4][0] = fma2(w1a.x, x0, fma2(w2p0, j0, acc[4][0]));
            acc[5][0] = fma2(w1a.y, x0, fma2(w2p1, j0, acc[5][0]));
            acc[6][0] = fma2(w1b.x, x0, fma2(w2p2, j0, acc[6][0]));
            acc[7][0] = fma2(w1b.y, x0, fma2(w2p3, j0, acc[7][0]));
            acc[4][1] = fma2(w1a.x, x1, fma2(w2p0, j1, acc[4][1]));
            acc[5][1] = fma2(w1a.y, x1, fma2(w2p1, j1, acc[5][1]));
            acc[6][1] = fma2(w1b.x, x1, fma2(w2p2, j1, acc[6][1]));
            acc[7][1] = fma2(w1b.y, x1, fma2(w2p3, j1, acc[7][1]));
        }
    }
    __syncthreads();

    // ---- stage acc -> smem -> coalesced global write ----
    float* sAcc = sm;                 // [64][276]
    #pragma unroll
    for (int k = 0; k < 8; k++) {
        int m = (k < 4) ? (mo2 + k) : (32 + mo2 + k - 4);
        *(u64*)&sAcc[m * P + pA] = acc[k][0];
        if (st1) *(u64*)&sAcc[m * P + pBr] = acc[k][1];
    }
    __syncthreads();
    {
        float* gA = g_Apart + (size_t)blk * M_MOL * P;
        #pragma unroll 4
        for (int idx = tid; idx < M_MOL * P; idx += NTHR) gA[idx] = sAcc[idx];
    }

    // ---- grid barrier (125 blocks co-resident) ----
    __threadfence();
    __syncthreads();
    if (tid == 0) {
        unsigned my = *(volatile unsigned*)&g_phase;
        int old = atomicAdd(&g_cnt, 1);
        if (old == NBLK - 1) {
            g_cnt = 0;
            __threadfence();
            atomicAdd(&g_phase, 1u);
        } else if (blk < M_MOL) {
            while (*(volatile unsigned*)&g_phase == my) __nanosleep(32);
        }
        __threadfence();
    }
    __syncthreads();
    if (blk >= M_MOL) return;

    // ---- post: reduce partials, Fs and Es for m = blk ----
    {
        const int m = blk;
        float* sFsx = sm;            // [276]
        float* sP   = sm + 512;      // [2][276]
        if (tid < 2 * P) {
            int h = tid / P;
            int p = tid - h * P;
            int b0 = h ? 63 : 0;
            int b1 = h ? NBLK : 63;
            const float* base = g_Apart + (size_t)m * P + p;
            float a0 = 0.f, a1 = 0.f, a2 = 0.f, a3 = 0.f;
            int b = b0;
            for (; b + 3 < b1; b += 4) {
                a0 += base[(size_t)(b    ) * M_MOL * P];
                a1 += base[(size_t)(b + 1) * M_MOL * P];
                a2 += base[(size_t)(b + 2) * M_MOL * P];
                a3 += base[(size_t)(b + 3) * M_MOL * P];
            }
            for (; b < b1; b++) a0 += base[(size_t)b * M_MOL * P];
            sP[h * P + p] = (a0 + a1) + (a2 + a3);
        }
        if (wid == 18) {
            float s1 = 0.0f, es = 0.0f;
            for (int b = lane; b < NBLK; b += 32) {
                s1 += g_S1part[b * M_MOL + m];
                es += g_Espart[b * M_MOL + m];
            }
            #pragma unroll
            for (int o = 16; o; o >>= 1) {
                s1 += __shfl_down_sync(0xffffffffu, s1, o);
                es += __shfl_down_sync(0xffffffffu, es, o);
            }
            if (lane == 0) {
                sm[1100] = s1;
                out[m] = es * (1.0f / QC);
            }
        }
        __syncthreads();
        if (tid < P) {
            int p = tid;
            int i = (int)(0.5f * (1.0f + sqrtf(8.0f * (float)p + 1.0f)));
            while (i * (i - 1) / 2 > p) i--;
            while ((i + 1) * i / 2 <= p) i++;
            int j = p - i * (i - 1) / 2;
            const float* a = Rs + (m * NA + i) * 3;
            const float* b = Rs + (m * NA + j) * 3;
            float dx = a[0] - b[0], dy = a[1] - b[1], dz = a[2] - b[2];
            float r2 = dx * dx + dy * dy + dz * dz;
            float xs = rsqrtf(r2);
            float qx = QC * xs;
            float asum = sP[p] + sP[P + p];
            sFsx[p] = (qx * sm[1100] - asum) * xs * xs * xs;
        }
        __syncthreads();
        if (tid < NA * 3) {
            int atom = tid / 3, d = tid % 3;
            float ra = Rs[(m * NA + atom) * 3 + d];
            float f = 0.0f;
            #pragma unroll
            for (int b = 0; b < NA; b++) {
                if (b == atom) continue;
                int hi = (atom > b) ? atom : b;
                int lo = (atom > b) ? b : atom;
                int pi = hi * (hi - 1) / 2 + lo;
                f = fmaf(Rs[(m * NA + b) * 3 + d] - ra, sFsx[pi], f);
            }
            out[M_MOL + (m * NA + atom) * 3 + d] = f;
        }
    }
}

// ---------------- entry ----------------
extern "C" void kernel_launch(void* const* d_in, const int* in_sizes, int n_in,
                              void* d_out, int out_size) {
    const float* Rs  = (const float*)d_in[0];
    const float* xst = (const float*)d_in[1];
    const float* Jx  = (const float*)d_in[2];
    float* out = (float*)d_out;

    cudaFuncSetAttribute(k_all, cudaFuncAttributeMaxDynamicSharedMemorySize, SMEM_BYTES);
    k_all<<<NBLK, NTHR, SMEM_BYTES>>>(Rs, xst, Jx, out);
}